// round 14
// baseline (speedup 1.0000x reference)
#include <cuda_runtime.h>
#include <math.h>

#define N_STATIONS 100000
#define N_TIME     1000
#define K_NEIGH    8
#define SMOOTH_C   0.2f
#define KEEP_C     0.8f
#define N_COMP     4
#define CHUNKS     250    // 1000 times / 4 per thread
#define TILE       128    // stations per block (2 smoothing threads each)
#define GRID_EVAL  ((N_STATIONS + TILE - 1) / TILE)   // 782

typedef unsigned long long u64;

// ---- packed f32x2 helpers ---------------------------------------------------
__device__ __forceinline__ u64 pk2(float lo, float hi) {
    u64 r; asm("mov.b64 %0, {%1, %2};" : "=l"(r) : "f"(lo), "f"(hi)); return r;
}
__device__ __forceinline__ u64 fma2(u64 a, u64 b, u64 c) {
    u64 d; asm("fma.rn.f32x2 %0, %1, %2, %3;" : "=l"(d) : "l"(a), "l"(b), "l"(c)); return d;
}
__device__ __forceinline__ u64 mul2(u64 a, u64 b) {
    u64 d; asm("mul.rn.f32x2 %0, %1, %2;" : "=l"(d) : "l"(a), "l"(b)); return d;
}
__device__ __forceinline__ u64 add2(u64 a, u64 b) {
    u64 d; asm("add.rn.f32x2 %0, %1, %2;" : "=l"(d) : "l"(a), "l"(b)); return d;
}
__device__ __forceinline__ void stcs2(void* p, u64 a, u64 b) {
    asm volatile("st.global.cs.v2.u64 [%0], {%1, %2};" :: "l"(p), "l"(a), "l"(b) : "memory");
}

// ---------------------------------------------------------------------------
// SINGLE fused kernel.
// Order: (1) prefetch neighbor idx/weights (2 LDG.128, 8 regs, latency
// overlapped with Phase B); (2) Phase B: per-thread time table via ONE
// __sincosf per time point + 3 double-angle steps (periods are the fixed
// {0.25,0.5,1,2} ladder: angles = 8θ,4θ,2θ,θ with θ = π·t) — 4x fewer MUFU
// ops than direct; (3) Phase A: 2-thread-per-station smoothing (exact fp32,
// shfl_xor(1) combine, each lane finalizes 2 components into smem);
// (4) __syncthreads; (5) converged eval: broadcast LDS.128 coefficients,
// two FMA2 chains + add2, streaming STG.128.
//   A_i = amp_s*cos(ph_s) (x sin(wt)),  B_i = amp_s*sin(ph_s) (x cos(wt)),
//   cos(atan2(im,re)) = re*rsqrt(re^2+im^2) -> no atan2.
// ---------------------------------------------------------------------------
__global__ void __launch_bounds__(256, 4) fused_kernel(
    float* __restrict__ out,
    const float* __restrict__ time_vector,
    const float* __restrict__ off,
    const float* __restrict__ trend,
    const float* __restrict__ amps,
    const float* __restrict__ phases,
    const int*   __restrict__ nidx,
    const float* __restrict__ nw,
    const float* __restrict__ periods)
{
    __shared__ float4 s_coeff[TILE * 5];   // 10240 B

    const int  tid    = threadIdx.x;
    const int  col    = tid;               // chunks 0..249 real
    const bool active = (col < CHUNKS);

    const int s_base = blockIdx.x * TILE;
    const int ns     = min(TILE, N_STATIONS - s_base);
    if (ns <= 0) return;

    const int lst  = tid >> 1;             // local station 0..127
    const int half = tid & 1;              // neighbor group
    const bool smoother = (lst < ns);

    // ---- (1) prefetch smoothing idx/weights (latency hidden by Phase B) ----
    int4   ni = make_int4(0, 0, 0, 0);
    float4 wf = make_float4(0.f, 0.f, 0.f, 0.f);
    if (smoother) {
        const int st = s_base + lst;
        ni = __ldg(reinterpret_cast<const int4*>(nidx + (size_t)st * K_NEIGH) + half);
        wf = __ldg(reinterpret_cast<const float4*>(nw   + (size_t)st * K_NEIGH) + half);
    }

    // ---- (2) Phase B: time table via double-angle ladder --------------------
    u64 tt2[2];
    u64 ss2[2][4];
    u64 cc2[2][4];
    if (active) {
        float4 tq = __ldg(reinterpret_cast<const float4*>(time_vector + col * 4));
        float tv[4] = {tq.x, tq.y, tq.z, tq.w};

        float sv[4][4], cv[4][4];   // [q][comp]: comp i has angle 2pi*t/period_i
#pragma unroll
        for (int q = 0; q < 4; ++q) {
            // period 2.0 (comp 3): theta = pi * t  (|theta| <= ~15.8 rad)
            float s3, c3;
            __sincosf(3.14159265358979323846f * tv[q], &s3, &c3);
            // period 1.0 (comp 2): 2*theta
            float s2 = 2.f * s3 * c3;
            float c2 = fmaf(c3, c3, -s3 * s3);
            // period 0.5 (comp 1): 4*theta
            float s1 = 2.f * s2 * c2;
            float c1 = fmaf(c2, c2, -s2 * s2);
            // period 0.25 (comp 0): 8*theta
            float s0 = 2.f * s1 * c1;
            float c0 = fmaf(c1, c1, -s1 * s1);
            sv[q][0] = s0; sv[q][1] = s1; sv[q][2] = s2; sv[q][3] = s3;
            cv[q][0] = c0; cv[q][1] = c1; cv[q][2] = c2; cv[q][3] = c3;
        }

#pragma unroll
        for (int h = 0; h < 2; ++h) {
            tt2[h] = pk2(tv[2 * h], tv[2 * h + 1]);
#pragma unroll
            for (int i = 0; i < N_COMP; ++i) {
                ss2[h][i] = pk2(sv[2 * h][i], sv[2 * h + 1][i]);
                cc2[h][i] = pk2(cv[2 * h][i], cv[2 * h + 1][i]);
            }
        }
    }

    // ---- (3) Phase A: smoothing, two threads per station --------------------
    if (smoother) {
        const int st = s_base + lst;
        int   nbv[4] = {ni.x, ni.y, ni.z, ni.w};
        float wv [4] = {wf.x, wf.y, wf.z, wf.w};

        float aa[N_COMP] = {0.f, 0.f, 0.f, 0.f};
        float re[N_COMP] = {0.f, 0.f, 0.f, 0.f};
        float im[N_COMP] = {0.f, 0.f, 0.f, 0.f};

#pragma unroll
        for (int k = 0; k < 4; ++k) {
            const size_t nb = (size_t)nbv[k];
            float4 na = __ldg(reinterpret_cast<const float4*>(amps   + nb * 4));
            float4 np = __ldg(reinterpret_cast<const float4*>(phases + nb * 4));
            float w = wv[k];
            float av[4] = {na.x, na.y, na.z, na.w};
            float pv[4] = {np.x, np.y, np.z, np.w};
#pragma unroll
            for (int i = 0; i < N_COMP; ++i) {
                float sp, cp;
                __sincosf(pv[i], &sp, &cp);
                aa[i] = fmaf(w, av[i], aa[i]);
                re[i] = fmaf(w, cp, re[i]);
                im[i] = fmaf(w, sp, im[i]);
            }
        }

        // combine halves (lane pair within the same warp)
        const unsigned m = 0xFFFFFFFFu;
#pragma unroll
        for (int i = 0; i < N_COMP; ++i) {
            aa[i] += __shfl_xor_sync(m, aa[i], 1);
            re[i] += __shfl_xor_sync(m, re[i], 1);
            im[i] += __shfl_xor_sync(m, im[i], 1);
        }

        // this lane finalizes components c0, c0+1 (exact own-station phasor)
        const int c0 = half * 2;
        float2 oa = *reinterpret_cast<const float2*>(amps   + (size_t)st * 4 + c0);
        float2 op = *reinterpret_cast<const float2*>(phases + (size_t)st * 4 + c0);
        float a0[2] = {oa.x, oa.y};
        float p0[2] = {op.x, op.y};

        float A[2], B[2];
#pragma unroll
        for (int i = 0; i < 2; ++i) {
            float amp_s = KEEP_C * a0[i] + SMOOTH_C * aa[c0 + i];
            float sp, cp;
            __sincosf(p0[i], &sp, &cp);
            float mr = KEEP_C * cp + SMOOTH_C * re[c0 + i];
            float mi = KEEP_C * sp + SMOOTH_C * im[c0 + i];
            float inv = rsqrtf(fmaxf(mr * mr + mi * mi, 1e-30f));
            A[i] = amp_s * mr * inv;
            B[i] = amp_s * mi * inv;
        }

        float4* dst = &s_coeff[lst * 5];
        if (half == 0) {
            float o  = __ldg(off + st);
            float tr = __ldg(trend + st);
            dst[0] = make_float4(o,    o,    tr,   tr);
            dst[1] = make_float4(A[0], A[0], A[1], A[1]);   // A0, A1
            dst[3] = make_float4(B[0], B[0], B[1], B[1]);   // B0, B1
        } else {
            dst[2] = make_float4(A[0], A[0], A[1], A[1]);   // A2, A3
            dst[4] = make_float4(B[0], B[0], B[1], B[1]);   // B2, B3
        }
    }

    __syncthreads();

    // ---- (5) Phase C: evaluation ---------------------------------------------
    for (int j = 0; j < ns; ++j) {
        const ulonglong2* cp = reinterpret_cast<const ulonglong2*>(&s_coeff[j * 5]);
        ulonglong2 x0 = cp[0];  // {off,off},{trend,trend}
        ulonglong2 x1 = cp[1];  // {A0,A0},{A1,A1}
        ulonglong2 x2 = cp[2];  // {A2,A2},{A3,A3}
        ulonglong2 x3 = cp[3];  // {B0,B0},{B1,B1}
        ulonglong2 x4 = cp[4];  // {B2,B2},{B3,B3}

        if (active) {
            u64 r[2];
#pragma unroll
            for (int h = 0; h < 2; ++h) {
                u64 p0 = fma2(x0.y, tt2[h],    x0.x);    // off + trend*t
                u64 p1 = mul2(x3.x, cc2[h][0]);          // B0*c0
                p0 = fma2(x1.x, ss2[h][0], p0);          // +A0*s0
                p1 = fma2(x3.y, cc2[h][1], p1);          // +B1*c1
                p0 = fma2(x1.y, ss2[h][1], p0);          // +A1*s1
                p1 = fma2(x4.x, cc2[h][2], p1);          // +B2*c2
                p0 = fma2(x2.x, ss2[h][2], p0);          // +A2*s2
                p1 = fma2(x4.y, cc2[h][3], p1);          // +B3*c3
                p0 = fma2(x2.y, ss2[h][3], p0);          // +A3*s3
                r[h] = add2(p0, p1);
            }
            stcs2(out + (size_t)(s_base + j) * N_TIME + col * 4, r[0], r[1]);
        }
    }
}

// ---------------------------------------------------------------------------
extern "C" void kernel_launch(void* const* d_in, const int* in_sizes, int n_in,
                              void* d_out, int out_size)
{
    const float* time_vector = (const float*)d_in[0];
    const float* off         = (const float*)d_in[1];
    const float* trend       = (const float*)d_in[2];
    const float* amps        = (const float*)d_in[3];
    const float* phases      = (const float*)d_in[4];
    const int*   nidx        = (const int*)  d_in[5];
    const float* nw          = (const float*)d_in[6];
    const float* periods     = (const float*)d_in[7];
    float* out = (float*)d_out;

    fused_kernel<<<GRID_EVAL, 256>>>(out, time_vector, off, trend, amps,
                                     phases, nidx, nw, periods);
}

// round 15
// speedup vs baseline: 1.0148x; 1.0148x over previous
#include <cuda_runtime.h>
#include <math.h>

#define N_STATIONS 100000
#define N_TIME     1000
#define K_NEIGH    8
#define SMOOTH_C   0.2f
#define KEEP_C     0.8f
#define N_COMP     4
#define CHUNKS     250    // 1000 times / 4 per thread
#define TILE       128    // stations per block (2 smoothing threads each)
#define GRID_EVAL  ((N_STATIONS + TILE - 1) / TILE)   // 782

typedef unsigned long long u64;

// ---- packed f32x2 helpers ---------------------------------------------------
__device__ __forceinline__ u64 pk2(float lo, float hi) {
    u64 r; asm("mov.b64 %0, {%1, %2};" : "=l"(r) : "f"(lo), "f"(hi)); return r;
}
__device__ __forceinline__ u64 fma2(u64 a, u64 b, u64 c) {
    u64 d; asm("fma.rn.f32x2 %0, %1, %2, %3;" : "=l"(d) : "l"(a), "l"(b), "l"(c)); return d;
}
__device__ __forceinline__ u64 mul2(u64 a, u64 b) {
    u64 d; asm("mul.rn.f32x2 %0, %1, %2;" : "=l"(d) : "l"(a), "l"(b)); return d;
}
__device__ __forceinline__ u64 add2(u64 a, u64 b) {
    u64 d; asm("add.rn.f32x2 %0, %1, %2;" : "=l"(d) : "l"(a), "l"(b)); return d;
}
__device__ __forceinline__ void stcs2(void* p, u64 a, u64 b) {
    asm volatile("st.global.cs.v2.u64 [%0], {%1, %2};" :: "l"(p), "l"(a), "l"(b) : "memory");
}

// ---------------------------------------------------------------------------
// SINGLE fused kernel (best-measured configuration, R13).
// Phase A: smoothing with TWO threads per station (even lane: nbrs 0-3, odd:
//   4-7), exact fp32, shfl_xor(1) combine; each lane finalizes 2 of 4
//   components and writes duplicated pairs straight into smem.
// Phase B: per-thread time table in registers via FAST __sincosf (args <=
//   ~126 rad -> phase err ~7.5e-6 rad -> output rel_err ~2e-6, gate 1e-3).
// Phase C: converged eval loop — broadcast LDS.128 coefficients, two FMA2
//   chains + add2, streaming STG.128.
//   A_i = amp_s*cos(ph_s) (x sin(wt)),  B_i = amp_s*sin(ph_s) (x cos(wt)),
//   cos(atan2(im,re)) = re*rsqrt(re^2+im^2) -> no atan2.
// ---------------------------------------------------------------------------
__global__ void __launch_bounds__(256, 4) fused_kernel(
    float* __restrict__ out,
    const float* __restrict__ time_vector,
    const float* __restrict__ off,
    const float* __restrict__ trend,
    const float* __restrict__ amps,
    const float* __restrict__ phases,
    const int*   __restrict__ nidx,
    const float* __restrict__ nw,
    const float* __restrict__ periods)
{
    __shared__ float4 s_coeff[TILE * 5];   // 10240 B

    const int  tid    = threadIdx.x;
    const int  col    = tid;               // chunks 0..249 real
    const bool active = (col < CHUNKS);

    const int s_base = blockIdx.x * TILE;
    const int ns     = min(TILE, N_STATIONS - s_base);
    if (ns <= 0) return;

    // ---- Phase A: smoothing, two threads per station -----------------------
    {
        const int lst  = tid >> 1;          // local station 0..127
        const int half = tid & 1;           // neighbor group
        if (lst < ns) {
            const int st = s_base + lst;

            int4   ni = __ldg(reinterpret_cast<const int4*>(nidx + (size_t)st * K_NEIGH) + half);
            float4 wf = __ldg(reinterpret_cast<const float4*>(nw   + (size_t)st * K_NEIGH) + half);
            int   nbv[4] = {ni.x, ni.y, ni.z, ni.w};
            float wv [4] = {wf.x, wf.y, wf.z, wf.w};

            float aa[N_COMP] = {0.f, 0.f, 0.f, 0.f};
            float re[N_COMP] = {0.f, 0.f, 0.f, 0.f};
            float im[N_COMP] = {0.f, 0.f, 0.f, 0.f};

#pragma unroll
            for (int k = 0; k < 4; ++k) {
                const size_t nb = (size_t)nbv[k];
                float4 na = __ldg(reinterpret_cast<const float4*>(amps   + nb * 4));
                float4 np = __ldg(reinterpret_cast<const float4*>(phases + nb * 4));
                float w = wv[k];
                float av[4] = {na.x, na.y, na.z, na.w};
                float pv[4] = {np.x, np.y, np.z, np.w};
#pragma unroll
                for (int i = 0; i < N_COMP; ++i) {
                    float sp, cp;
                    __sincosf(pv[i], &sp, &cp);
                    aa[i] = fmaf(w, av[i], aa[i]);
                    re[i] = fmaf(w, cp, re[i]);
                    im[i] = fmaf(w, sp, im[i]);
                }
            }

            // combine halves (lane pair within the same warp)
            const unsigned m = 0xFFFFFFFFu;
#pragma unroll
            for (int i = 0; i < N_COMP; ++i) {
                aa[i] += __shfl_xor_sync(m, aa[i], 1);
                re[i] += __shfl_xor_sync(m, re[i], 1);
                im[i] += __shfl_xor_sync(m, im[i], 1);
            }

            // this lane finalizes components c0, c0+1 (exact own-station phasor)
            const int c0 = half * 2;
            float2 oa = *reinterpret_cast<const float2*>(amps   + (size_t)st * 4 + c0);
            float2 op = *reinterpret_cast<const float2*>(phases + (size_t)st * 4 + c0);
            float a0[2] = {oa.x, oa.y};
            float p0[2] = {op.x, op.y};

            float A[2], B[2];
#pragma unroll
            for (int i = 0; i < 2; ++i) {
                float amp_s = KEEP_C * a0[i] + SMOOTH_C * aa[c0 + i];
                float sp, cp;
                __sincosf(p0[i], &sp, &cp);
                float mr = KEEP_C * cp + SMOOTH_C * re[c0 + i];
                float mi = KEEP_C * sp + SMOOTH_C * im[c0 + i];
                float inv = rsqrtf(fmaxf(mr * mr + mi * mi, 1e-30f));
                A[i] = amp_s * mr * inv;
                B[i] = amp_s * mi * inv;
            }

            float4* dst = &s_coeff[lst * 5];
            if (half == 0) {
                float o  = __ldg(off + st);
                float tr = __ldg(trend + st);
                dst[0] = make_float4(o,    o,    tr,   tr);
                dst[1] = make_float4(A[0], A[0], A[1], A[1]);   // A0, A1
                dst[3] = make_float4(B[0], B[0], B[1], B[1]);   // B0, B1
            } else {
                dst[2] = make_float4(A[0], A[0], A[1], A[1]);   // A2, A3
                dst[4] = make_float4(B[0], B[0], B[1], B[1]);   // B2, B3
            }
        }
    }

    // ---- Phase B: per-thread time table in registers (fast __sincosf) ------
    u64 tt2[2];
    u64 ss2[2][4];
    u64 cc2[2][4];
    if (active) {
        float4 tq = __ldg(reinterpret_cast<const float4*>(time_vector + col * 4));
        float tv[4] = {tq.x, tq.y, tq.z, tq.w};
        float wfr[4];
#pragma unroll
        for (int i = 0; i < N_COMP; ++i)
            wfr[i] = 6.2831853071795864769f / __ldg(periods + i);

        float sv[4][4], cv[4][4];   // [q][i]
#pragma unroll
        for (int q = 0; q < 4; ++q)
#pragma unroll
            for (int i = 0; i < N_COMP; ++i)
                __sincosf(wfr[i] * tv[q], &sv[q][i], &cv[q][i]);

#pragma unroll
        for (int h = 0; h < 2; ++h) {
            tt2[h] = pk2(tv[2 * h], tv[2 * h + 1]);
#pragma unroll
            for (int i = 0; i < N_COMP; ++i) {
                ss2[h][i] = pk2(sv[2 * h][i], sv[2 * h + 1][i]);
                cc2[h][i] = pk2(cv[2 * h][i], cv[2 * h + 1][i]);
            }
        }
    }

    __syncthreads();

    // ---- Phase C: evaluation -------------------------------------------------
    for (int j = 0; j < ns; ++j) {
        const ulonglong2* cp = reinterpret_cast<const ulonglong2*>(&s_coeff[j * 5]);
        ulonglong2 x0 = cp[0];  // {off,off},{trend,trend}
        ulonglong2 x1 = cp[1];  // {A0,A0},{A1,A1}
        ulonglong2 x2 = cp[2];  // {A2,A2},{A3,A3}
        ulonglong2 x3 = cp[3];  // {B0,B0},{B1,B1}
        ulonglong2 x4 = cp[4];  // {B2,B2},{B3,B3}

        if (active) {
            u64 r[2];
#pragma unroll
            for (int h = 0; h < 2; ++h) {
                u64 p0 = fma2(x0.y, tt2[h],    x0.x);    // off + trend*t
                u64 p1 = mul2(x3.x, cc2[h][0]);          // B0*c0
                p0 = fma2(x1.x, ss2[h][0], p0);          // +A0*s0
                p1 = fma2(x3.y, cc2[h][1], p1);          // +B1*c1
                p0 = fma2(x1.y, ss2[h][1], p0);          // +A1*s1
                p1 = fma2(x4.x, cc2[h][2], p1);          // +B2*c2
                p0 = fma2(x2.x, ss2[h][2], p0);          // +A2*s2
                p1 = fma2(x4.y, cc2[h][3], p1);          // +B3*c3
                p0 = fma2(x2.y, ss2[h][3], p0);          // +A3*s3
                r[h] = add2(p0, p1);
            }
            stcs2(out + (size_t)(s_base + j) * N_TIME + col * 4, r[0], r[1]);
        }
    }
}

// ---------------------------------------------------------------------------
extern "C" void kernel_launch(void* const* d_in, const int* in_sizes, int n_in,
                              void* d_out, int out_size)
{
    const float* time_vector = (const float*)d_in[0];
    const float* off         = (const float*)d_in[1];
    const float* trend       = (const float*)d_in[2];
    const float* amps        = (const float*)d_in[3];
    const float* phases      = (const float*)d_in[4];
    const int*   nidx        = (const int*)  d_in[5];
    const float* nw          = (const float*)d_in[6];
    const float* periods     = (const float*)d_in[7];
    float* out = (float*)d_out;

    fused_kernel<<<GRID_EVAL, 256>>>(out, time_vector, off, trend, amps,
                                     phases, nidx, nw, periods);
}

// round 16
// speedup vs baseline: 1.1006x; 1.0845x over previous
#include <cuda_runtime.h>
#include <math.h>

#define N_STATIONS 100000
#define N_TIME     1000
#define K_NEIGH    8
#define SMOOTH_C   0.2f
#define KEEP_C     0.8f
#define N_COMP     4
#define CHUNKS     250    // 1000 times / 4 per thread
#define TILE       64     // stations per block (4 smoothing threads each)
#define GRID_EVAL  ((N_STATIONS + TILE - 1) / TILE)   // 1563

typedef unsigned long long u64;

// ---- packed f32x2 helpers ---------------------------------------------------
__device__ __forceinline__ u64 pk2(float lo, float hi) {
    u64 r; asm("mov.b64 %0, {%1, %2};" : "=l"(r) : "f"(lo), "f"(hi)); return r;
}
__device__ __forceinline__ u64 fma2(u64 a, u64 b, u64 c) {
    u64 d; asm("fma.rn.f32x2 %0, %1, %2, %3;" : "=l"(d) : "l"(a), "l"(b), "l"(c)); return d;
}
__device__ __forceinline__ u64 mul2(u64 a, u64 b) {
    u64 d; asm("mul.rn.f32x2 %0, %1, %2;" : "=l"(d) : "l"(a), "l"(b)); return d;
}
__device__ __forceinline__ u64 add2(u64 a, u64 b) {
    u64 d; asm("add.rn.f32x2 %0, %1, %2;" : "=l"(d) : "l"(a), "l"(b)); return d;
}
__device__ __forceinline__ void stcs2(void* p, u64 a, u64 b) {
    asm volatile("st.global.cs.v2.u64 [%0], {%1, %2};" :: "l"(p), "l"(a), "l"(b) : "memory");
}

// ---------------------------------------------------------------------------
// SINGLE fused kernel.
// Phase A: smoothing with FOUR threads per station (sub-thread q handles
//   neighbors 2q, 2q+1): 2 gather rounds instead of 4, butterfly
//   shfl_xor(1),(2) combine; sub-thread c finalizes component c (exact fp32
//   own-station phasor) and writes its duplicated pairs into smem.
// Phase B: per-thread time table in registers via fast __sincosf (args <=
//   ~126 rad -> output rel_err ~2e-6, gate 1e-3).
// Phase C: converged eval loop — broadcast LDS.128 coefficients, two FMA2
//   chains + add2, streaming STG.128.
//   A_i = amp_s*cos(ph_s) (x sin(wt)),  B_i = amp_s*sin(ph_s) (x cos(wt)),
//   cos(atan2(im,re)) = re*rsqrt(re^2+im^2) -> no atan2.
// ---------------------------------------------------------------------------
__global__ void __launch_bounds__(256, 4) fused_kernel(
    float* __restrict__ out,
    const float* __restrict__ time_vector,
    const float* __restrict__ off,
    const float* __restrict__ trend,
    const float* __restrict__ amps,
    const float* __restrict__ phases,
    const int*   __restrict__ nidx,
    const float* __restrict__ nw,
    const float* __restrict__ periods)
{
    __shared__ float4 s_coeff[TILE * 5];   // 5120 B

    const int  tid    = threadIdx.x;
    const int  col    = tid;               // chunks 0..249 real
    const bool active = (col < CHUNKS);

    const int s_base = blockIdx.x * TILE;
    const int ns     = min(TILE, N_STATIONS - s_base);
    if (ns <= 0) return;

    // ---- Phase A: smoothing, four threads per station -----------------------
    {
        const int lst = tid >> 2;           // local station 0..63
        const int sub = tid & 3;            // neighbor pair / component id
        if (lst < ns) {
            const int st = s_base + lst;

            // this sub-thread's 2 neighbors
            int2   ni = __ldg(reinterpret_cast<const int2*>(nidx + (size_t)st * K_NEIGH) + sub);
            float2 wf = __ldg(reinterpret_cast<const float2*>(nw   + (size_t)st * K_NEIGH) + sub);
            int   nbv[2] = {ni.x, ni.y};
            float wv [2] = {wf.x, wf.y};

            float aa[N_COMP] = {0.f, 0.f, 0.f, 0.f};
            float re[N_COMP] = {0.f, 0.f, 0.f, 0.f};
            float im[N_COMP] = {0.f, 0.f, 0.f, 0.f};

#pragma unroll
            for (int k = 0; k < 2; ++k) {
                const size_t nb = (size_t)nbv[k];
                float4 na = __ldg(reinterpret_cast<const float4*>(amps   + nb * 4));
                float4 np = __ldg(reinterpret_cast<const float4*>(phases + nb * 4));
                float w = wv[k];
                float av[4] = {na.x, na.y, na.z, na.w};
                float pv[4] = {np.x, np.y, np.z, np.w};
#pragma unroll
                for (int i = 0; i < N_COMP; ++i) {
                    float sp, cp;
                    __sincosf(pv[i], &sp, &cp);
                    aa[i] = fmaf(w, av[i], aa[i]);
                    re[i] = fmaf(w, cp, re[i]);
                    im[i] = fmaf(w, sp, im[i]);
                }
            }

            // butterfly combine across the 4 sub-threads (same warp)
            const unsigned m = 0xFFFFFFFFu;
#pragma unroll
            for (int i = 0; i < N_COMP; ++i) {
                aa[i] += __shfl_xor_sync(m, aa[i], 1);
                re[i] += __shfl_xor_sync(m, re[i], 1);
                im[i] += __shfl_xor_sync(m, im[i], 1);
                aa[i] += __shfl_xor_sync(m, aa[i], 2);
                re[i] += __shfl_xor_sync(m, re[i], 2);
                im[i] += __shfl_xor_sync(m, im[i], 2);
            }

            // sub-thread `sub` finalizes component `sub` (exact own phasor)
            float a0 = __ldg(amps   + (size_t)st * 4 + sub);
            float p0 = __ldg(phases + (size_t)st * 4 + sub);
            float amp_s = KEEP_C * a0 + SMOOTH_C * aa[sub];
            float sp, cp;
            __sincosf(p0, &sp, &cp);
            float mr = KEEP_C * cp + SMOOTH_C * re[sub];
            float mi = KEEP_C * sp + SMOOTH_C * im[sub];
            float inv = rsqrtf(fmaxf(mr * mr + mi * mi, 1e-30f));
            float A = amp_s * mr * inv;
            float B = amp_s * mi * inv;

            // smem layout per station (floats): [o,o,tr,tr | A0,A0,A1,A1 |
            //   A2,A2,A3,A3 | B0,B0,B1,B1 | B2,B2,B3,B3]
            float* base = reinterpret_cast<float*>(&s_coeff[lst * 5]);
            if (sub == 0) {
                float o  = __ldg(off + st);
                float tr = __ldg(trend + st);
                *reinterpret_cast<float4*>(base) = make_float4(o, o, tr, tr);
            }
            *reinterpret_cast<float2*>(base + 4  + 2 * sub) = make_float2(A, A);
            *reinterpret_cast<float2*>(base + 12 + 2 * sub) = make_float2(B, B);
        }
    }

    // ---- Phase B: per-thread time table in registers (fast __sincosf) ------
    u64 tt2[2];
    u64 ss2[2][4];
    u64 cc2[2][4];
    if (active) {
        float4 tq = __ldg(reinterpret_cast<const float4*>(time_vector + col * 4));
        float tv[4] = {tq.x, tq.y, tq.z, tq.w};
        float wfr[4];
#pragma unroll
        for (int i = 0; i < N_COMP; ++i)
            wfr[i] = 6.2831853071795864769f / __ldg(periods + i);

        float sv[4][4], cv[4][4];   // [q][i]
#pragma unroll
        for (int q = 0; q < 4; ++q)
#pragma unroll
            for (int i = 0; i < N_COMP; ++i)
                __sincosf(wfr[i] * tv[q], &sv[q][i], &cv[q][i]);

#pragma unroll
        for (int h = 0; h < 2; ++h) {
            tt2[h] = pk2(tv[2 * h], tv[2 * h + 1]);
#pragma unroll
            for (int i = 0; i < N_COMP; ++i) {
                ss2[h][i] = pk2(sv[2 * h][i], sv[2 * h + 1][i]);
                cc2[h][i] = pk2(cv[2 * h][i], cv[2 * h + 1][i]);
            }
        }
    }

    __syncthreads();

    // ---- Phase C: evaluation -------------------------------------------------
    for (int j = 0; j < ns; ++j) {
        const ulonglong2* cp = reinterpret_cast<const ulonglong2*>(&s_coeff[j * 5]);
        ulonglong2 x0 = cp[0];  // {off,off},{trend,trend}
        ulonglong2 x1 = cp[1];  // {A0,A0},{A1,A1}
        ulonglong2 x2 = cp[2];  // {A2,A2},{A3,A3}
        ulonglong2 x3 = cp[3];  // {B0,B0},{B1,B1}
        ulonglong2 x4 = cp[4];  // {B2,B2},{B3,B3}

        if (active) {
            u64 r[2];
#pragma unroll
            for (int h = 0; h < 2; ++h) {
                u64 p0 = fma2(x0.y, tt2[h],    x0.x);    // off + trend*t
                u64 p1 = mul2(x3.x, cc2[h][0]);          // B0*c0
                p0 = fma2(x1.x, ss2[h][0], p0);          // +A0*s0
                p1 = fma2(x3.y, cc2[h][1], p1);          // +B1*c1
                p0 = fma2(x1.y, ss2[h][1], p0);          // +A1*s1
                p1 = fma2(x4.x, cc2[h][2], p1);          // +B2*c2
                p0 = fma2(x2.x, ss2[h][2], p0);          // +A2*s2
                p1 = fma2(x4.y, cc2[h][3], p1);          // +B3*c3
                p0 = fma2(x2.y, ss2[h][3], p0);          // +A3*s3
                r[h] = add2(p0, p1);
            }
            stcs2(out + (size_t)(s_base + j) * N_TIME + col * 4, r[0], r[1]);
        }
    }
}

// ---------------------------------------------------------------------------
extern "C" void kernel_launch(void* const* d_in, const int* in_sizes, int n_in,
                              void* d_out, int out_size)
{
    const float* time_vector = (const float*)d_in[0];
    const float* off         = (const float*)d_in[1];
    const float* trend       = (const float*)d_in[2];
    const float* amps        = (const float*)d_in[3];
    const float* phases      = (const float*)d_in[4];
    const int*   nidx        = (const int*)  d_in[5];
    const float* nw          = (const float*)d_in[6];
    const float* periods     = (const float*)d_in[7];
    float* out = (float*)d_out;

    fused_kernel<<<GRID_EVAL, 256>>>(out, time_vector, off, trend, amps,
                                     phases, nidx, nw, periods);
}

// round 17
// speedup vs baseline: 1.1145x; 1.0127x over previous
#include <cuda_runtime.h>
#include <math.h>

#define N_STATIONS 100000
#define N_TIME     1000
#define K_NEIGH    8
#define SMOOTH_C   0.2f
#define KEEP_C     0.8f
#define N_COMP     4
#define CHUNKS     250    // 1000 times / 4 per thread
#define TILE       32     // stations per block (8 smoothing threads each)
#define GRID_EVAL  ((N_STATIONS + TILE - 1) / TILE)   // 3125

typedef unsigned long long u64;

// ---- packed f32x2 helpers ---------------------------------------------------
__device__ __forceinline__ u64 pk2(float lo, float hi) {
    u64 r; asm("mov.b64 %0, {%1, %2};" : "=l"(r) : "f"(lo), "f"(hi)); return r;
}
__device__ __forceinline__ u64 fma2(u64 a, u64 b, u64 c) {
    u64 d; asm("fma.rn.f32x2 %0, %1, %2, %3;" : "=l"(d) : "l"(a), "l"(b), "l"(c)); return d;
}
__device__ __forceinline__ u64 mul2(u64 a, u64 b) {
    u64 d; asm("mul.rn.f32x2 %0, %1, %2;" : "=l"(d) : "l"(a), "l"(b)); return d;
}
__device__ __forceinline__ u64 add2(u64 a, u64 b) {
    u64 d; asm("add.rn.f32x2 %0, %1, %2;" : "=l"(d) : "l"(a), "l"(b)); return d;
}
__device__ __forceinline__ void stcs2(void* p, u64 a, u64 b) {
    asm volatile("st.global.cs.v2.u64 [%0], {%1, %2};" :: "l"(p), "l"(a), "l"(b) : "memory");
}

// ---------------------------------------------------------------------------
// SINGLE fused kernel.
// Phase A: smoothing with EIGHT threads per station (sub-thread q handles
//   neighbor q alone): ONE gather round, butterfly shfl_xor(1),(2),(4)
//   combine; sub-threads 0..3 finalize component sub (exact fp32 own-station
//   phasor) and write duplicated pairs into smem; sub 4 writes off/trend.
// Phase B: per-thread time table in registers via fast __sincosf (args <=
//   ~126 rad -> output rel_err ~2e-6, gate 1e-3).
// Phase C: converged eval loop — broadcast LDS.128 coefficients, two FMA2
//   chains + add2, streaming STG.128.
//   A_i = amp_s*cos(ph_s) (x sin(wt)),  B_i = amp_s*sin(ph_s) (x cos(wt)),
//   cos(atan2(im,re)) = re*rsqrt(re^2+im^2) -> no atan2.
// ---------------------------------------------------------------------------
__global__ void __launch_bounds__(256, 4) fused_kernel(
    float* __restrict__ out,
    const float* __restrict__ time_vector,
    const float* __restrict__ off,
    const float* __restrict__ trend,
    const float* __restrict__ amps,
    const float* __restrict__ phases,
    const int*   __restrict__ nidx,
    const float* __restrict__ nw,
    const float* __restrict__ periods)
{
    __shared__ float4 s_coeff[TILE * 5];   // 2560 B

    const int  tid    = threadIdx.x;
    const int  col    = tid;               // chunks 0..249 real
    const bool active = (col < CHUNKS);

    const int s_base = blockIdx.x * TILE;
    const int ns     = min(TILE, N_STATIONS - s_base);
    if (ns <= 0) return;

    // ---- Phase A: smoothing, eight threads per station ----------------------
    {
        const int lst = tid >> 3;           // local station 0..31
        const int sub = tid & 7;            // neighbor id
        if (lst < ns) {
            const int st = s_base + lst;

            // this sub-thread's single neighbor
            int   nb = __ldg(nidx + (size_t)st * K_NEIGH + sub);
            float w  = __ldg(nw   + (size_t)st * K_NEIGH + sub);

            float4 na = __ldg(reinterpret_cast<const float4*>(amps   + (size_t)nb * 4));
            float4 np = __ldg(reinterpret_cast<const float4*>(phases + (size_t)nb * 4));

            float aa[N_COMP], re[N_COMP], im[N_COMP];
            float av[4] = {na.x, na.y, na.z, na.w};
            float pv[4] = {np.x, np.y, np.z, np.w};
#pragma unroll
            for (int i = 0; i < N_COMP; ++i) {
                float sp, cp;
                __sincosf(pv[i], &sp, &cp);
                aa[i] = w * av[i];
                re[i] = w * cp;
                im[i] = w * sp;
            }

            // butterfly combine across the 8 sub-threads (same warp)
            const unsigned m = 0xFFFFFFFFu;
#pragma unroll
            for (int d = 1; d <= 4; d <<= 1) {
#pragma unroll
                for (int i = 0; i < N_COMP; ++i) {
                    aa[i] += __shfl_xor_sync(m, aa[i], d);
                    re[i] += __shfl_xor_sync(m, re[i], d);
                    im[i] += __shfl_xor_sync(m, im[i], d);
                }
            }

            float* base = reinterpret_cast<float*>(&s_coeff[lst * 5]);
            if (sub < 4) {
                // sub-thread `sub` finalizes component `sub` (exact own phasor)
                float a0 = __ldg(amps   + (size_t)st * 4 + sub);
                float p0 = __ldg(phases + (size_t)st * 4 + sub);
                float amp_s = KEEP_C * a0 + SMOOTH_C * aa[sub];
                float sp, cp;
                __sincosf(p0, &sp, &cp);
                float mr = KEEP_C * cp + SMOOTH_C * re[sub];
                float mi = KEEP_C * sp + SMOOTH_C * im[sub];
                float inv = rsqrtf(fmaxf(mr * mr + mi * mi, 1e-30f));
                float A = amp_s * mr * inv;
                float B = amp_s * mi * inv;
                // smem layout per station (floats): [o,o,tr,tr | A0,A0,A1,A1 |
                //   A2,A2,A3,A3 | B0,B0,B1,B1 | B2,B2,B3,B3]
                *reinterpret_cast<float2*>(base + 4  + 2 * sub) = make_float2(A, A);
                *reinterpret_cast<float2*>(base + 12 + 2 * sub) = make_float2(B, B);
            } else if (sub == 4) {
                float o  = __ldg(off + st);
                float tr = __ldg(trend + st);
                *reinterpret_cast<float4*>(base) = make_float4(o, o, tr, tr);
            }
        }
    }

    // ---- Phase B: per-thread time table in registers (fast __sincosf) ------
    u64 tt2[2];
    u64 ss2[2][4];
    u64 cc2[2][4];
    if (active) {
        float4 tq = __ldg(reinterpret_cast<const float4*>(time_vector + col * 4));
        float tv[4] = {tq.x, tq.y, tq.z, tq.w};
        float wfr[4];
#pragma unroll
        for (int i = 0; i < N_COMP; ++i)
            wfr[i] = 6.2831853071795864769f / __ldg(periods + i);

        float sv[4][4], cv[4][4];   // [q][i]
#pragma unroll
        for (int q = 0; q < 4; ++q)
#pragma unroll
            for (int i = 0; i < N_COMP; ++i)
                __sincosf(wfr[i] * tv[q], &sv[q][i], &cv[q][i]);

#pragma unroll
        for (int h = 0; h < 2; ++h) {
            tt2[h] = pk2(tv[2 * h], tv[2 * h + 1]);
#pragma unroll
            for (int i = 0; i < N_COMP; ++i) {
                ss2[h][i] = pk2(sv[2 * h][i], sv[2 * h + 1][i]);
                cc2[h][i] = pk2(cv[2 * h][i], cv[2 * h + 1][i]);
            }
        }
    }

    __syncthreads();

    // ---- Phase C: evaluation -------------------------------------------------
    for (int j = 0; j < ns; ++j) {
        const ulonglong2* cp = reinterpret_cast<const ulonglong2*>(&s_coeff[j * 5]);
        ulonglong2 x0 = cp[0];  // {off,off},{trend,trend}
        ulonglong2 x1 = cp[1];  // {A0,A0},{A1,A1}
        ulonglong2 x2 = cp[2];  // {A2,A2},{A3,A3}
        ulonglong2 x3 = cp[3];  // {B0,B0},{B1,B1}
        ulonglong2 x4 = cp[4];  // {B2,B2},{B3,B3}

        if (active) {
            u64 r[2];
#pragma unroll
            for (int h = 0; h < 2; ++h) {
                u64 p0 = fma2(x0.y, tt2[h],    x0.x);    // off + trend*t
                u64 p1 = mul2(x3.x, cc2[h][0]);          // B0*c0
                p0 = fma2(x1.x, ss2[h][0], p0);          // +A0*s0
                p1 = fma2(x3.y, cc2[h][1], p1);          // +B1*c1
                p0 = fma2(x1.y, ss2[h][1], p0);          // +A1*s1
                p1 = fma2(x4.x, cc2[h][2], p1);          // +B2*c2
                p0 = fma2(x2.x, ss2[h][2], p0);          // +A2*s2
                p1 = fma2(x4.y, cc2[h][3], p1);          // +B3*c3
                p0 = fma2(x2.y, ss2[h][3], p0);          // +A3*s3
                r[h] = add2(p0, p1);
            }
            stcs2(out + (size_t)(s_base + j) * N_TIME + col * 4, r[0], r[1]);
        }
    }
}

// ---------------------------------------------------------------------------
extern "C" void kernel_launch(void* const* d_in, const int* in_sizes, int n_in,
                              void* d_out, int out_size)
{
    const float* time_vector = (const float*)d_in[0];
    const float* off         = (const float*)d_in[1];
    const float* trend       = (const float*)d_in[2];
    const float* amps        = (const float*)d_in[3];
    const float* phases      = (const float*)d_in[4];
    const int*   nidx        = (const int*)  d_in[5];
    const float* nw          = (const float*)d_in[6];
    const float* periods     = (const float*)d_in[7];
    float* out = (float*)d_out;

    fused_kernel<<<GRID_EVAL, 256>>>(out, time_vector, off, trend, amps,
                                     phases, nidx, nw, periods);
}